// round 5
// baseline (speedup 1.0000x reference)
#include <cuda_runtime.h>
#include <cstddef>

#define S_IMG  2048
#define S_TXT  512
#define S_TOT  2560
#define DMODEL 1536
#define NH     24
#define DH     64

// ---------------- scratch (no allocations allowed) ----------------
__device__ float g_Q[NH * S_TOT * DH];   // [h][s][d]
__device__ float g_K[NH * S_TOT * DH];
__device__ float g_V[NH * S_TOT * DH];
__device__ float g_O[S_TOT * DMODEL];    // [s][h*64+d]

// ---------------- GEMM: Y[m][n] = sum_k A[m][k] * W[n][k] + bias[n] ----------------
// MODE 0: scatter into head layout out[((n/64)*S_TOT + s_off + m)*64 + n%64]
// MODE 1: linear out[m*1536 + n]
// Tiles: BM=BN=128, BK=8, 256 threads, 8x8 micro-tile per thread.
// Software-pipelined: next k-tile's LDGs issue before the FMA loop.
template<int MODE>
__global__ __launch_bounds__(256)
void gemm128(const float* __restrict__ A, const float* __restrict__ W,
             const float* __restrict__ bias, float* __restrict__ out, int s_off)
{
    __shared__ float As[8][132];
    __shared__ float Bs[8][132];
    const int tid  = threadIdx.x;
    const int trow = tid >> 4;        // 0..15
    const int tcol = tid & 15;        // 0..15
    const int arow = tid >> 1;        // 0..127
    const int acol = (tid & 1) << 2;  // 0 or 4

    const float* Ap = A + (size_t)(blockIdx.y * 128 + arow) * DMODEL + acol;
    const float* Wp = W + (size_t)(blockIdx.x * 128 + arow) * DMODEL + acol;

    float acc[8][8] = {};

    float4 av = *(const float4*)(Ap);
    float4 wv = *(const float4*)(Wp);

    for (int k0 = 0; k0 < DMODEL; k0 += 8) {
        As[acol + 0][arow] = av.x; As[acol + 1][arow] = av.y;
        As[acol + 2][arow] = av.z; As[acol + 3][arow] = av.w;
        Bs[acol + 0][arow] = wv.x; Bs[acol + 1][arow] = wv.y;
        Bs[acol + 2][arow] = wv.z; Bs[acol + 3][arow] = wv.w;
        __syncthreads();

        if (k0 + 8 < DMODEL) {                    // prefetch next tile (overlaps FMAs)
            av = *(const float4*)(Ap + k0 + 8);
            wv = *(const float4*)(Wp + k0 + 8);
        }

        #pragma unroll
        for (int kk = 0; kk < 8; kk++) {
            float a[8], b[8];
            *(float4*)&a[0] = *(const float4*)&As[kk][trow * 8];
            *(float4*)&a[4] = *(const float4*)&As[kk][trow * 8 + 4];
            *(float4*)&b[0] = *(const float4*)&Bs[kk][tcol * 8];
            *(float4*)&b[4] = *(const float4*)&Bs[kk][tcol * 8 + 4];
            #pragma unroll
            for (int i = 0; i < 8; i++)
                #pragma unroll
                for (int j = 0; j < 8; j++)
                    acc[i][j] = fmaf(a[i], b[j], acc[i][j]);
        }
        __syncthreads();
    }

    const int m0 = blockIdx.y * 128 + trow * 8;
    const int n0 = blockIdx.x * 128 + tcol * 8;
    float bv[8];
    #pragma unroll
    for (int j = 0; j < 8; j++) bv[j] = bias[n0 + j];

    if (MODE == 0) {
        const int h = n0 >> 6, d0 = n0 & 63;   // 8-col group never crosses a head boundary
        #pragma unroll
        for (int i = 0; i < 8; i++) {
            const int s = s_off + m0 + i;
            float* p = out + (((size_t)h * S_TOT + s) << 6) + d0;
            *(float4*)p       = make_float4(acc[i][0] + bv[0], acc[i][1] + bv[1],
                                            acc[i][2] + bv[2], acc[i][3] + bv[3]);
            *(float4*)(p + 4) = make_float4(acc[i][4] + bv[4], acc[i][5] + bv[5],
                                            acc[i][6] + bv[6], acc[i][7] + bv[7]);
        }
    } else {
        #pragma unroll
        for (int i = 0; i < 8; i++) {
            float* p = out + (size_t)(m0 + i) * DMODEL + n0;
            *(float4*)p       = make_float4(acc[i][0] + bv[0], acc[i][1] + bv[1],
                                            acc[i][2] + bv[2], acc[i][3] + bv[3]);
            *(float4*)(p + 4) = make_float4(acc[i][4] + bv[4], acc[i][5] + bv[5],
                                            acc[i][6] + bv[6], acc[i][7] + bv[7]);
        }
    }
}

// ---------------- RMS-norm (per head-dim row) + gain + RoPE ----------------
// One warp handles one (h,s) row of 64 elements (2 per lane).
// Text rows (s < S_TXT) use g_txt, image rows use g_img.
__global__ __launch_bounds__(128)
void rmsrope(float* __restrict__ buf, const float* __restrict__ g_txt,
             const float* __restrict__ g_img, const float* __restrict__ rcos,
             const float* __restrict__ rsin)
{
    const int warp = threadIdx.x >> 5;
    const int lane = threadIdx.x & 31;
    const int row  = blockIdx.x * 4 + warp;     // 0 .. NH*S_TOT-1
    const int s    = row % S_TOT;

    float2 x = *(float2*)&buf[(size_t)row * 64 + lane * 2];
    float ss = x.x * x.x + x.y * x.y;
    #pragma unroll
    for (int off = 16; off > 0; off >>= 1)
        ss += __shfl_xor_sync(0xffffffffu, ss, off);
    const float r = rsqrtf(ss * (1.0f / 64.0f) + 1e-6f);

    const float* g = (s < S_TXT) ? g_txt : g_img;
    const float y0 = x.x * r * g[lane * 2];
    const float y1 = x.y * r * g[lane * 2 + 1];
    const float c  = rcos[s * 64 + lane * 2];   // repeated pairwise
    const float sn = rsin[s * 64 + lane * 2];
    const float o0 = y0 * c - y1 * sn;
    const float o1 = y1 * c + y0 * sn;
    *(float2*)&buf[(size_t)row * 64 + lane * 2] = make_float2(o0, o1);
}

// ---------------- fp32 flash attention ----------------
// grid (S_TOT/64, NH), 256 threads (16x16), 4x4 micro-tiles.
// Shared: Qs[64][64] | Ks[64][65] | Vs[64][64] | Ps[64][64]  (dynamic, 65792 B)
#define FLASH_SMEM ((64 * 64 + 64 * 65 + 64 * 64 + 64 * 64) * 4)

__global__ __launch_bounds__(256)
void flash(const float* __restrict__ Qb, const float* __restrict__ Kb,
           const float* __restrict__ Vb, float* __restrict__ O)
{
    extern __shared__ float sm[];
    float* Qs = sm;                 // stride 64 (broadcast reads only)
    float* Ks = Qs + 64 * 64;       // stride 65 (lane-strided scalar reads)
    float* Vs = Ks + 64 * 65;       // stride 64 (float4 reads)
    float* Ps = Vs + 64 * 64;       // stride 64

    const int tid = threadIdx.x;
    const int ty  = tid >> 4;       // q micro-row group
    const int tx  = tid & 15;       // k / d micro-col group
    const int h   = blockIdx.y;
    const int q0  = blockIdx.x * 64;

    const float* Qg = Qb + (((size_t)h * S_TOT + q0) << 6);
    const float* Kg = Kb + (((size_t)h * S_TOT) << 6);
    const float* Vg = Vb + (((size_t)h * S_TOT) << 6);

    // Load Q tile, pre-scaled by DH^-0.5
    #pragma unroll
    for (int t = tid; t < 1024; t += 256) {
        const int r = t >> 4, c = (t & 15) << 2;
        float4 v = *(const float4*)(Qg + r * 64 + c);
        v.x *= 0.125f; v.y *= 0.125f; v.z *= 0.125f; v.w *= 0.125f;
        *(float4*)&Qs[r * 64 + c] = v;
    }

    float m[4], l[4], acc[4][4];
    #pragma unroll
    for (int i = 0; i < 4; i++) {
        m[i] = -1e30f; l[i] = 0.0f;
        #pragma unroll
        for (int j = 0; j < 4; j++) acc[i][j] = 0.0f;
    }

    for (int kt = 0; kt < S_TOT / 64; kt++) {
        __syncthreads();   // previous PV done before overwriting K/V
        #pragma unroll
        for (int t = tid; t < 1024; t += 256) {
            const int r = t >> 4, c = (t & 15) << 2;
            float4 kv = *(const float4*)(Kg + (kt * 64 + r) * 64 + c);
            Ks[r * 65 + c + 0] = kv.x; Ks[r * 65 + c + 1] = kv.y;
            Ks[r * 65 + c + 2] = kv.z; Ks[r * 65 + c + 3] = kv.w;
            *(float4*)&Vs[r * 64 + c] = *(const float4*)(Vg + (kt * 64 + r) * 64 + c);
        }
        __syncthreads();

        // S = Q K^T  (pre-scaled)
        float s4[4][4] = {};
        #pragma unroll 4
        for (int d = 0; d < 64; d++) {
            float qv[4], kv[4];
            #pragma unroll
            for (int i = 0; i < 4; i++) qv[i] = Qs[(4 * ty + i) * 64 + d];
            #pragma unroll
            for (int j = 0; j < 4; j++) kv[j] = Ks[(4 * tx + j) * 65 + d];
            #pragma unroll
            for (int i = 0; i < 4; i++)
                #pragma unroll
                for (int j = 0; j < 4; j++)
                    s4[i][j] = fmaf(qv[i], kv[j], s4[i][j]);
        }

        // online softmax (row reductions over the 16 tx lanes = half-warp)
        #pragma unroll
        for (int i = 0; i < 4; i++) {
            float tm = fmaxf(fmaxf(s4[i][0], s4[i][1]), fmaxf(s4[i][2], s4[i][3]));
            #pragma unroll
            for (int off = 8; off > 0; off >>= 1)
                tm = fmaxf(tm, __shfl_xor_sync(0xffffffffu, tm, off));
            const float mn   = fmaxf(m[i], tm);
            const float corr = __expf(m[i] - mn);
            float p[4], rs = 0.0f;
            #pragma unroll
            for (int j = 0; j < 4; j++) { p[j] = __expf(s4[i][j] - mn); rs += p[j]; }
            #pragma unroll
            for (int off = 8; off > 0; off >>= 1)
                rs += __shfl_xor_sync(0xffffffffu, rs, off);
            l[i] = l[i] * corr + rs;
            m[i] = mn;
            #pragma unroll
            for (int j = 0; j < 4; j++) acc[i][j] *= corr;
            *(float4*)&Ps[(4 * ty + i) * 64 + 4 * tx] = make_float4(p[0], p[1], p[2], p[3]);
        }
        __syncthreads();

        // O += P V
        #pragma unroll 4
        for (int k = 0; k < 64; k++) {
            float pv[4];
            #pragma unroll
            for (int i = 0; i < 4; i++) pv[i] = Ps[(4 * ty + i) * 64 + k];
            const float4 vv = *(const float4*)&Vs[k * 64 + 4 * tx];
            #pragma unroll
            for (int i = 0; i < 4; i++) {
                acc[i][0] = fmaf(pv[i], vv.x, acc[i][0]);
                acc[i][1] = fmaf(pv[i], vv.y, acc[i][1]);
                acc[i][2] = fmaf(pv[i], vv.z, acc[i][2]);
                acc[i][3] = fmaf(pv[i], vv.w, acc[i][3]);
            }
        }
    }

    // write O[s][h*64+d]
    float* Og = O + (size_t)q0 * DMODEL + h * 64;
    #pragma unroll
    for (int i = 0; i < 4; i++) {
        const float inv = 1.0f / l[i];
        *(float4*)(Og + (size_t)(4 * ty + i) * DMODEL + 4 * tx) =
            make_float4(acc[i][0] * inv, acc[i][1] * inv, acc[i][2] * inv, acc[i][3] * inv);
    }
}

// ---------------- launch ----------------
extern "C" void kernel_launch(void* const* d_in, const int* in_sizes, int n_in,
                              void* d_out, int out_size)
{
    const float* hid  = (const float*)d_in[0];
    const float* enc  = (const float*)d_in[1];
    const float* rcos = (const float*)d_in[2];
    const float* rsin = (const float*)d_in[3];
    const float* Wq  = (const float*)d_in[4];  const float* bq  = (const float*)d_in[5];
    const float* Wk  = (const float*)d_in[6];  const float* bk  = (const float*)d_in[7];
    const float* Wv  = (const float*)d_in[8];  const float* bv  = (const float*)d_in[9];
    const float* Waq = (const float*)d_in[10]; const float* baq = (const float*)d_in[11];
    const float* Wak = (const float*)d_in[12]; const float* bak = (const float*)d_in[13];
    const float* Wav = (const float*)d_in[14]; const float* bav = (const float*)d_in[15];
    const float* Wo  = (const float*)d_in[16]; const float* bo  = (const float*)d_in[17];
    const float* Wao = (const float*)d_in[18]; const float* bao = (const float*)d_in[19];
    const float* gq  = (const float*)d_in[20]; const float* gk  = (const float*)d_in[21];
    const float* gaq = (const float*)d_in[22]; const float* gak = (const float*)d_in[23];
    float* out = (float*)d_out;

    float *Qp, *Kp, *Vp, *Op;
    cudaGetSymbolAddress((void**)&Qp, g_Q);
    cudaGetSymbolAddress((void**)&Kp, g_K);
    cudaGetSymbolAddress((void**)&Vp, g_V);
    cudaGetSymbolAddress((void**)&Op, g_O);

    const dim3 gImg(DMODEL / 128, S_IMG / 128);   // 12 x 16
    const dim3 gTxt(DMODEL / 128, S_TXT / 128);   // 12 x 4

    // QKV projections -> head layout [h][s][d]; text at s=0..511, image at 512..2559
    gemm128<0><<<gImg, 256>>>(hid, Wq,  bq,  Qp, S_TXT);
    gemm128<0><<<gImg, 256>>>(hid, Wk,  bk,  Kp, S_TXT);
    gemm128<0><<<gImg, 256>>>(hid, Wv,  bv,  Vp, S_TXT);
    gemm128<0><<<gTxt, 256>>>(enc, Waq, baq, Qp, 0);
    gemm128<0><<<gTxt, 256>>>(enc, Wak, bak, Kp, 0);
    gemm128<0><<<gTxt, 256>>>(enc, Wav, bav, Vp, 0);

    // RMS norm + gain + RoPE on Q and K
    rmsrope<<<NH * S_TOT / 4, 128>>>(Qp, gaq, gq, rcos, rsin);
    rmsrope<<<NH * S_TOT / 4, 128>>>(Kp, gak, gk, rcos, rsin);

    // flash attention -> O[s][h*64+d]
    cudaFuncSetAttribute(flash, cudaFuncAttributeMaxDynamicSharedMemorySize, FLASH_SMEM);
    flash<<<dim3(S_TOT / 64, NH), 256, FLASH_SMEM>>>(Qp, Kp, Vp, Op);

    // output projections: img_out first (2048x1536), then enc_out (512x1536)
    gemm128<1><<<gImg, 256>>>(Op + (size_t)S_TXT * DMODEL, Wo,  bo,  out, 0);
    gemm128<1><<<gTxt, 256>>>(Op,                          Wao, bao, out + (size_t)S_IMG * DMODEL, 0);
}

// round 6
// speedup vs baseline: 2.1139x; 2.1139x over previous
#include <cuda_runtime.h>
#include <cstddef>

#define S_IMG  2048
#define S_TXT  512
#define S_TOT  2560
#define DMODEL 1536
#define NH     24
#define DH     64

typedef unsigned long long ull;

// ---------------- packed fp32x2 helpers (sm_103a FFMA2 path) ----------------
__device__ __forceinline__ ull fma2(ull a, ull b, ull c) {
    ull d; asm("fma.rn.f32x2 %0, %1, %2, %3;" : "=l"(d) : "l"(a), "l"(b), "l"(c)); return d;
}
__device__ __forceinline__ ull mul2(ull a, ull b) {
    ull d; asm("mul.rn.f32x2 %0, %1, %2;" : "=l"(d) : "l"(a), "l"(b)); return d;
}
__device__ __forceinline__ ull pack2(float x, float y) {
    ull d; asm("mov.b64 %0, {%1, %2};" : "=l"(d) : "f"(x), "f"(y)); return d;
}
__device__ __forceinline__ float2 unpack2(ull v) {
    float x, y; asm("mov.b64 {%0, %1}, %2;" : "=f"(x), "=f"(y) : "l"(v));
    return make_float2(x, y);
}

// ---------------- scratch (no allocations allowed) ----------------
__device__ float g_Q[NH * S_TOT * DH];   // [h][s][d]
__device__ float g_K[NH * S_TOT * DH];
__device__ float g_V[NH * S_TOT * DH];
__device__ float g_O[S_TOT * DMODEL];    // [s][h*64+d]

// ================= GEMM core =================
// Y[m][n] = sum_k A[m][k] * W[n][k] + bias[n]
// BM=BN=128, BK=8, 256 threads, 8x8 per thread via FFMA2 (j-paired accumulators).
// As2 holds the A tile with every value DUPLICATED (a,a) so dup-pairs load as 64-bit.
struct GemmOut {
    ull acc2[8][4];
};

__device__ __forceinline__ void gemm_core(const float* __restrict__ A,
                                          const float* __restrict__ W,
                                          float* As2 /*[8][264]*/, float* Bs /*[8][132]*/,
                                          GemmOut& G)
{
    const int tid  = threadIdx.x;
    const int trow = tid >> 4;
    const int tcol = tid & 15;
    const int arow = tid >> 1;
    const int acol = (tid & 1) << 2;

    const float* Ap = A + (size_t)arow * DMODEL + acol;
    const float* Wp = W + (size_t)arow * DMODEL + acol;

    #pragma unroll
    for (int i = 0; i < 8; i++)
        #pragma unroll
        for (int j = 0; j < 4; j++) G.acc2[i][j] = 0ull;

    float4 av = *(const float4*)(Ap);
    float4 wv = *(const float4*)(Wp);

    for (int k0 = 0; k0 < DMODEL; k0 += 8) {
        // stage A duplicated, B plain (transposed into [k][row] layout)
        *(ull*)&As2[(acol + 0) * 264 + arow * 2] = pack2(av.x, av.x);
        *(ull*)&As2[(acol + 1) * 264 + arow * 2] = pack2(av.y, av.y);
        *(ull*)&As2[(acol + 2) * 264 + arow * 2] = pack2(av.z, av.z);
        *(ull*)&As2[(acol + 3) * 264 + arow * 2] = pack2(av.w, av.w);
        Bs[(acol + 0) * 132 + arow] = wv.x;
        Bs[(acol + 1) * 132 + arow] = wv.y;
        Bs[(acol + 2) * 132 + arow] = wv.z;
        Bs[(acol + 3) * 132 + arow] = wv.w;
        __syncthreads();

        if (k0 + 8 < DMODEL) {                    // prefetch next tile
            av = *(const float4*)(Ap + k0 + 8);
            wv = *(const float4*)(Wp + k0 + 8);
        }

        #pragma unroll
        for (int kk = 0; kk < 8; kk++) {
            // a dup-pairs: (a0,a0),(a1,a1),... directly from smem
            ulonglong2 a01 = *(const ulonglong2*)&As2[kk * 264 + trow * 16];
            ulonglong2 a23 = *(const ulonglong2*)&As2[kk * 264 + trow * 16 + 4];
            ulonglong2 a45 = *(const ulonglong2*)&As2[kk * 264 + trow * 16 + 8];
            ulonglong2 a67 = *(const ulonglong2*)&As2[kk * 264 + trow * 16 + 12];
            // b pairs: (b0,b1),(b2,b3),(b4,b5),(b6,b7)
            ulonglong2 b03 = *(const ulonglong2*)&Bs[kk * 132 + tcol * 8];
            ulonglong2 b47 = *(const ulonglong2*)&Bs[kk * 132 + tcol * 8 + 4];
            ull ad[8] = {a01.x, a01.y, a23.x, a23.y, a45.x, a45.y, a67.x, a67.y};
            ull bp[4] = {b03.x, b03.y, b47.x, b47.y};
            #pragma unroll
            for (int i = 0; i < 8; i++)
                #pragma unroll
                for (int j = 0; j < 4; j++)
                    G.acc2[i][j] = fma2(ad[i], bp[j], G.acc2[i][j]);
        }
        __syncthreads();
    }
}

// ---------------- fused QKV projection ----------------
// grid.x = 36 (12 n-tiles x {Q,K,V}), grid.y = 20 (2560 rows: txt tiles 0..3, img 4..19)
__global__ __launch_bounds__(256, 2)
void gemm_qkv(const float* __restrict__ hid, const float* __restrict__ enc,
              const float* __restrict__ Wq,  const float* __restrict__ Wk,  const float* __restrict__ Wv,
              const float* __restrict__ Waq, const float* __restrict__ Wak, const float* __restrict__ Wav,
              const float* __restrict__ bq,  const float* __restrict__ bk,  const float* __restrict__ bv,
              const float* __restrict__ baq, const float* __restrict__ bak, const float* __restrict__ bav,
              float* __restrict__ Qp, float* __restrict__ Kp, float* __restrict__ Vp)
{
    __shared__ float As2[8 * 264];
    __shared__ float Bs [8 * 132];

    const int nt   = blockIdx.x;
    const int mt   = blockIdx.y;
    const int proj = nt / 12;                 // 0=Q 1=K 2=V
    const int n0b  = (nt % 12) * 128;         // column tile within 1536
    const bool txt = (mt < 4);

    const float* A;
    if (txt) A = enc + (size_t)(mt * 128) * DMODEL;
    else     A = hid + (size_t)(mt * 128 - S_TXT) * DMODEL;

    const float* W    = txt ? (proj == 0 ? Waq : proj == 1 ? Wak : Wav)
                            : (proj == 0 ? Wq  : proj == 1 ? Wk  : Wv);
    const float* bias = txt ? (proj == 0 ? baq : proj == 1 ? bak : bav)
                            : (proj == 0 ? bq  : proj == 1 ? bk  : bv);
    float* out = proj == 0 ? Qp : proj == 1 ? Kp : Vp;

    GemmOut G;
    gemm_core(A, W + (size_t)n0b * DMODEL, As2, Bs, G);

    const int trow = threadIdx.x >> 4;
    const int tcol = threadIdx.x & 15;
    const int n0   = n0b + tcol * 8;          // global column, 8 cols never cross a head
    const int h    = n0 >> 6, d0 = n0 & 63;
    float bvv[8];
    #pragma unroll
    for (int j = 0; j < 8; j++) bvv[j] = bias[n0 + j];

    #pragma unroll
    for (int i = 0; i < 8; i++) {
        const int s = mt * 128 + trow * 8 + i;    // txt occupies s 0..511, img 512..2559
        float* p = out + (((size_t)h * S_TOT + s) << 6) + d0;
        float2 c0 = unpack2(G.acc2[i][0]), c1 = unpack2(G.acc2[i][1]);
        float2 c2 = unpack2(G.acc2[i][2]), c3 = unpack2(G.acc2[i][3]);
        *(float4*)p       = make_float4(c0.x + bvv[0], c0.y + bvv[1], c1.x + bvv[2], c1.y + bvv[3]);
        *(float4*)(p + 4) = make_float4(c2.x + bvv[4], c2.y + bvv[5], c3.x + bvv[6], c3.y + bvv[7]);
    }
}

// ---------------- fused output projection ----------------
// d_out rows: img (0..2047, from g_O rows 512..2559 via Wo), enc (2048..2559, g_O rows 0..511 via Wao)
__global__ __launch_bounds__(256, 2)
void gemm_out(const float* __restrict__ Op,
              const float* __restrict__ Wo, const float* __restrict__ Wao,
              const float* __restrict__ bo, const float* __restrict__ bao,
              float* __restrict__ out)
{
    __shared__ float As2[8 * 264];
    __shared__ float Bs [8 * 132];

    const int nt = blockIdx.x;                // 12
    const int mt = blockIdx.y;                // 20 over output rows
    const int r0 = mt * 128;
    const bool img = (r0 < S_IMG);

    const float* A    = img ? Op + (size_t)(S_TXT + r0) * DMODEL
                            : Op + (size_t)(r0 - S_IMG) * DMODEL;
    const float* W    = img ? Wo : Wao;
    const float* bias = img ? bo : bao;

    GemmOut G;
    gemm_core(A, W + (size_t)(nt * 128) * DMODEL, As2, Bs, G);

    const int trow = threadIdx.x >> 4;
    const int tcol = threadIdx.x & 15;
    const int n0   = nt * 128 + tcol * 8;
    float bvv[8];
    #pragma unroll
    for (int j = 0; j < 8; j++) bvv[j] = bias[n0 + j];

    #pragma unroll
    for (int i = 0; i < 8; i++) {
        float* p = out + (size_t)(r0 + trow * 8 + i) * DMODEL + n0;
        float2 c0 = unpack2(G.acc2[i][0]), c1 = unpack2(G.acc2[i][1]);
        float2 c2 = unpack2(G.acc2[i][2]), c3 = unpack2(G.acc2[i][3]);
        *(float4*)p       = make_float4(c0.x + bvv[0], c0.y + bvv[1], c1.x + bvv[2], c1.y + bvv[3]);
        *(float4*)(p + 4) = make_float4(c2.x + bvv[4], c2.y + bvv[5], c3.x + bvv[6], c3.y + bvv[7]);
    }
}

// ---------------- RMS-norm + gain + RoPE ----------------
__global__ __launch_bounds__(128)
void rmsrope(float* __restrict__ buf, const float* __restrict__ g_txt,
             const float* __restrict__ g_img, const float* __restrict__ rcos,
             const float* __restrict__ rsin)
{
    const int warp = threadIdx.x >> 5;
    const int lane = threadIdx.x & 31;
    const int row  = blockIdx.x * 4 + warp;
    const int s    = row % S_TOT;

    float2 x = *(float2*)&buf[(size_t)row * 64 + lane * 2];
    float ss = x.x * x.x + x.y * x.y;
    #pragma unroll
    for (int off = 16; off > 0; off >>= 1)
        ss += __shfl_xor_sync(0xffffffffu, ss, off);
    const float r = rsqrtf(ss * (1.0f / 64.0f) + 1e-6f);

    const float* g = (s < S_TXT) ? g_txt : g_img;
    const float y0 = x.x * r * g[lane * 2];
    const float y1 = x.y * r * g[lane * 2 + 1];
    const float c  = rcos[s * 64 + lane * 2];
    const float sn = rsin[s * 64 + lane * 2];
    *(float2*)&buf[(size_t)row * 64 + lane * 2] =
        make_float2(y0 * c - y1 * sn, y1 * c + y0 * sn);
}

// ---------------- fp32 flash attention (FFMA2) ----------------
// grid (S_TOT/64, NH), 256 threads (16x16), 4x4 micro-tiles.
// Qt transposed [d][r] stride 66; Ks [r][d] stride 65; Vs/Ps stride 64.
#define FLASH_SMEM ((64 * 66 + 64 * 65 + 64 * 64 + 64 * 64) * 4)

__global__ __launch_bounds__(256)
void flash(const float* __restrict__ Qb, const float* __restrict__ Kb,
           const float* __restrict__ Vb, float* __restrict__ O)
{
    extern __shared__ float sm[];
    float* Qt = sm;                  // [64 d][66]
    float* Ks = Qt + 64 * 66;        // [64 r][65]
    float* Vs = Ks + 64 * 65;        // [64 r][64]
    float* Ps = Vs + 64 * 64;        // [64 r][64]

    const int tid = threadIdx.x;
    const int ty  = tid >> 4;
    const int tx  = tid & 15;
    const int h   = blockIdx.y;
    const int q0  = blockIdx.x * 64;

    const float* Qg = Qb + (((size_t)h * S_TOT + q0) << 6);
    const float* Kg = Kb + (((size_t)h * S_TOT) << 6);
    const float* Vg = Vb + (((size_t)h * S_TOT) << 6);

    // Load Q tile transposed, pre-scaled by DH^-0.5
    #pragma unroll
    for (int t = tid; t < 1024; t += 256) {
        const int r = t >> 4, c = (t & 15) << 2;
        float4 v = *(const float4*)(Qg + r * 64 + c);
        Qt[(c + 0) * 66 + r] = v.x * 0.125f;
        Qt[(c + 1) * 66 + r] = v.y * 0.125f;
        Qt[(c + 2) * 66 + r] = v.z * 0.125f;
        Qt[(c + 3) * 66 + r] = v.w * 0.125f;
    }

    float m[4], l[4];
    ull  o2[4][2];                   // O accum, cols paired
    #pragma unroll
    for (int i = 0; i < 4; i++) {
        m[i] = -1e30f; l[i] = 0.0f;
        o2[i][0] = 0ull; o2[i][1] = 0ull;
    }

    for (int kt = 0; kt < S_TOT / 64; kt++) {
        __syncthreads();
        #pragma unroll
        for (int t = tid; t < 1024; t += 256) {
            const int r = t >> 4, c = (t & 15) << 2;
            float4 kv = *(const float4*)(Kg + (kt * 64 + r) * 64 + c);
            Ks[r * 65 + c + 0] = kv.x; Ks[r * 65 + c + 1] = kv.y;
            Ks[r * 65 + c + 2] = kv.z; Ks[r * 65 + c + 3] = kv.w;
            *(float4*)&Vs[r * 64 + c] = *(const float4*)(Vg + (kt * 64 + r) * 64 + c);
        }
        __syncthreads();

        // S = Q K^T : rows paired via transposed Q
        ull s2[2][4];
        #pragma unroll
        for (int p = 0; p < 2; p++)
            #pragma unroll
            for (int j = 0; j < 4; j++) s2[p][j] = 0ull;

        #pragma unroll 4
        for (int d = 0; d < 64; d++) {
            const ull q01 = *(const ull*)&Qt[d * 66 + 4 * ty];
            const ull q23 = *(const ull*)&Qt[d * 66 + 4 * ty + 2];
            #pragma unroll
            for (int j = 0; j < 4; j++) {
                const float kv = Ks[(4 * tx + j) * 65 + d];
                const ull kd = pack2(kv, kv);
                s2[0][j] = fma2(q01, kd, s2[0][j]);
                s2[1][j] = fma2(q23, kd, s2[1][j]);
            }
        }

        float s4[4][4];
        #pragma unroll
        for (int p = 0; p < 2; p++)
            #pragma unroll
            for (int j = 0; j < 4; j++) {
                float2 v = unpack2(s2[p][j]);
                s4[2 * p][j] = v.x; s4[2 * p + 1][j] = v.y;
            }

        // online softmax (reduction across the 16 tx lanes)
        #pragma unroll
        for (int i = 0; i < 4; i++) {
            float tm = fmaxf(fmaxf(s4[i][0], s4[i][1]), fmaxf(s4[i][2], s4[i][3]));
            #pragma unroll
            for (int off = 8; off > 0; off >>= 1)
                tm = fmaxf(tm, __shfl_xor_sync(0xffffffffu, tm, off));
            const float mn   = fmaxf(m[i], tm);
            const float corr = __expf(m[i] - mn);
            float p0 = __expf(s4[i][0] - mn), p1 = __expf(s4[i][1] - mn);
            float p2 = __expf(s4[i][2] - mn), p3 = __expf(s4[i][3] - mn);
            float rs = p0 + p1 + p2 + p3;
            #pragma unroll
            for (int off = 8; off > 0; off >>= 1)
                rs += __shfl_xor_sync(0xffffffffu, rs, off);
            l[i] = l[i] * corr + rs;
            m[i] = mn;
            const ull c2 = pack2(corr, corr);
            o2[i][0] = mul2(o2[i][0], c2);
            o2[i][1] = mul2(o2[i][1], c2);
            *(float4*)&Ps[(4 * ty + i) * 64 + 4 * tx] = make_float4(p0, p1, p2, p3);
        }
        __syncthreads();

        // O += P V  (V cols paired naturally)
        #pragma unroll 4
        for (int k = 0; k < 64; k++) {
            const ulonglong2 vv = *(const ulonglong2*)&Vs[k * 64 + 4 * tx];
            #pragma unroll
            for (int i = 0; i < 4; i++) {
                const float pv = Ps[(4 * ty + i) * 64 + k];
                const ull pd = pack2(pv, pv);
                o2[i][0] = fma2(pd, vv.x, o2[i][0]);
                o2[i][1] = fma2(pd, vv.y, o2[i][1]);
            }
        }
    }

    // write O[s][h*64+d]
    float* Og = O + (size_t)q0 * DMODEL + h * 64;
    #pragma unroll
    for (int i = 0; i < 4; i++) {
        const float inv = 1.0f / l[i];
        float2 a = unpack2(o2[i][0]), b = unpack2(o2[i][1]);
        *(float4*)(Og + (size_t)(4 * ty + i) * DMODEL + 4 * tx) =
            make_float4(a.x * inv, a.y * inv, b.x * inv, b.y * inv);
    }
}

// ---------------- launch ----------------
extern "C" void kernel_launch(void* const* d_in, const int* in_sizes, int n_in,
                              void* d_out, int out_size)
{
    const float* hid  = (const float*)d_in[0];
    const float* enc  = (const float*)d_in[1];
    const float* rcos = (const float*)d_in[2];
    const float* rsin = (const float*)d_in[3];
    const float* Wq  = (const float*)d_in[4];  const float* bq  = (const float*)d_in[5];
    const float* Wk  = (const float*)d_in[6];  const float* bk  = (const float*)d_in[7];
    const float* Wv  = (const float*)d_in[8];  const float* bv  = (const float*)d_in[9];
    const float* Waq = (const float*)d_in[10]; const float* baq = (const float*)d_in[11];
    const float* Wak = (const float*)d_in[12]; const float* bak = (const float*)d_in[13];
    const float* Wav = (const float*)d_in[14]; const float* bav = (const float*)d_in[15];
    const float* Wo  = (const float*)d_in[16]; const float* bo  = (const float*)d_in[17];
    const float* Wao = (const float*)d_in[18]; const float* bao = (const float*)d_in[19];
    const float* gq  = (const float*)d_in[20]; const float* gk  = (const float*)d_in[21];
    const float* gaq = (const float*)d_in[22]; const float* gak = (const float*)d_in[23];
    float* out = (float*)d_out;

    float *Qp, *Kp, *Vp, *Op;
    cudaGetSymbolAddress((void**)&Qp, g_Q);
    cudaGetSymbolAddress((void**)&Kp, g_K);
    cudaGetSymbolAddress((void**)&Vp, g_V);
    cudaGetSymbolAddress((void**)&Op, g_O);

    // fused QKV projections -> head layout [h][s][d]
    gemm_qkv<<<dim3(36, 20), 256>>>(hid, enc, Wq, Wk, Wv, Waq, Wak, Wav,
                                    bq, bk, bv, baq, bak, bav, Qp, Kp, Vp);

    // RMS norm + gain + RoPE on Q and K
    rmsrope<<<NH * S_TOT / 4, 128>>>(Qp, gaq, gq, rcos, rsin);
    rmsrope<<<NH * S_TOT / 4, 128>>>(Kp, gak, gk, rcos, rsin);

    // flash attention -> O[s][h*64+d]
    cudaFuncSetAttribute(flash, cudaFuncAttributeMaxDynamicSharedMemorySize, FLASH_SMEM);
    flash<<<dim3(S_TOT / 64, NH), 256, FLASH_SMEM>>>(Qp, Kp, Vp, Op);

    // fused output projections
    gemm_out<<<dim3(12, 20), 256>>>(Op, Wo, Wao, bo, bao, out);
}